// round 1
// baseline (speedup 1.0000x reference)
#include <cuda_runtime.h>

// Problem constants (fixed shapes)
#define NN   65536      // total nodes
#define BB   64         // graphs
#define NPGc 1024       // nodes per graph
#define CCc  512        // feature dim
#define EEc  2097152    // edges
#define DEc  16         // edge feat dim
#define KKc  512        // k = ceil(0.5*1024)
#define BKc  32768      // B*k

// Output layout (float32, concatenated in reference-return order)
#define OFF_XNEW  0LL                       // [BK, C]   = 16777216
#define OFF_EI    16777216LL                // [2, E]    =  4194304
#define OFF_EA    20971520LL                // [E, DE]   = 33554432
#define OFF_MASK  54525952LL                // [E]       =  2097152
#define OFF_BATCH 56623104LL                // [BK]      =    32768
#define OFF_PERM  56655872LL                // [BK]      =    32768

// Scratch (device globals; allocation-free)
__device__ float g_h[NN];       // h, then h*dinv
__device__ float g_dinv[NN];
__device__ float g_score[NN];
__device__ float g_deg[NN];
__device__ int   g_newidx[NN];
__device__ int   g_perm[BKc];

// K1: h = x @ W (warp per row); init deg=1 (self loop), newidx=-1
__global__ void k_proj(const float* __restrict__ x, const float* __restrict__ W) {
    int warp = (blockIdx.x * blockDim.x + threadIdx.x) >> 5;
    int lane = threadIdx.x & 31;
    if (warp >= NN) return;
    const float4* xr = (const float4*)(x + (size_t)warp * CCc);
    const float4* w4 = (const float4*)W;
    float s = 0.f;
#pragma unroll
    for (int i = 0; i < 4; i++) {
        float4 a = xr[lane + i * 32];
        float4 w = w4[lane + i * 32];
        s += a.x * w.x + a.y * w.y + a.z * w.z + a.w * w.w;
    }
#pragma unroll
    for (int o = 16; o; o >>= 1) s += __shfl_down_sync(0xffffffffu, s, o);
    if (lane == 0) {
        g_h[warp] = s;
        g_deg[warp] = 1.0f;
        g_newidx[warp] = -1;
    }
}

// K2: in-degree accumulation over dst
__global__ void k_deg(const int* __restrict__ dst) {
    int e = blockIdx.x * blockDim.x + threadIdx.x;
    if (e < EEc) atomicAdd(&g_deg[dst[e]], 1.0f);
}

// K3: dinv = 1/sqrt(deg); hd = h*dinv; score = self-loop term + b
__global__ void k_dinv(const float* __restrict__ b) {
    int i = blockIdx.x * blockDim.x + threadIdx.x;
    if (i >= NN) return;
    float dv = 1.0f / sqrtf(g_deg[i]);
    g_dinv[i] = dv;
    float hd = g_h[i] * dv;
    g_h[i] = hd;
    g_score[i] = hd * dv + b[0];
}

// K4: score[d] += hd[s] * dinv[d] over edges
__global__ void k_scatter(const int* __restrict__ src, const int* __restrict__ dst) {
    int e = blockIdx.x * blockDim.x + threadIdx.x;
    if (e >= EEc) return;
    int s = src[e], d = dst[e];
    atomicAdd(&g_score[d], g_h[s] * g_dinv[d]);
}

// K5: per-graph top-k via 1024-element bitonic sort of (descending score, ascending idx)
__global__ void k_topk(float* __restrict__ out) {
    __shared__ unsigned long long keys[NPGc];
    int g = blockIdx.x, t = threadIdx.x;
    int node = g * NPGc + t;
    float sc = g_score[node];
    unsigned int u = __float_as_uint(sc);
    u = (u & 0x80000000u) ? ~u : (u | 0x80000000u);  // monotone: ascending uint == ascending float
    u = ~u;                                          // flip -> ascending key == descending score
    keys[t] = ((unsigned long long)u << 32) | (unsigned int)t;
    __syncthreads();
    for (int k = 2; k <= NPGc; k <<= 1) {
        for (int j = k >> 1; j > 0; j >>= 1) {
            int ixj = t ^ j;
            if (ixj > t) {
                bool up = ((t & k) == 0);
                unsigned long long a = keys[t], bb = keys[ixj];
                if ((a > bb) == up) { keys[t] = bb; keys[ixj] = a; }
            }
            __syncthreads();
        }
    }
    if (t < KKc) {
        int li = (int)(keys[t] & 0xFFFFFFFFu);
        int n2 = g * NPGc + li;
        int p = g * KKc + t;
        g_perm[p] = n2;
        g_newidx[n2] = p;
        out[OFF_PERM + p]  = (float)n2;
        out[OFF_BATCH + p] = (float)g;
    }
}

// K6: x_new = x[perm] * tanh(score[perm]) ; 128 threads per row (float4 each)
__global__ void k_gather(const float* __restrict__ x, float* __restrict__ out) {
    int row  = blockIdx.x * 2 + (threadIdx.x >> 7);
    int col4 = threadIdx.x & 127;
    int srcn = g_perm[row];
    float sc = tanhf(g_score[srcn]);
    float4 v = ((const float4*)(x + (size_t)srcn * CCc))[col4];
    v.x *= sc; v.y *= sc; v.z *= sc; v.w *= sc;
    ((float4*)(out + OFF_XNEW + (size_t)row * CCc))[col4] = v;
}

// K7: edge remap + mask
__global__ void k_edges(const int* __restrict__ src, const int* __restrict__ dst,
                        float* __restrict__ out) {
    int e = blockIdx.x * blockDim.x + threadIdx.x;
    if (e >= EEc) return;
    int ns = g_newidx[src[e]];
    int nd = g_newidx[dst[e]];
    bool m = (ns >= 0) && (nd >= 0);
    out[OFF_EI + e]        = m ? (float)ns : -1.0f;
    out[OFF_EI + EEc + e]  = m ? (float)nd : -1.0f;
    out[OFF_MASK + e]      = m ? 1.0f : 0.0f;
}

// K8: ea_new = mask ? edge_attr : 0  (float4 granularity, 4 threads per edge)
__global__ void k_ea(const float* __restrict__ ea, float* __restrict__ out) {
    int i = blockIdx.x * blockDim.x + threadIdx.x;  // over E*DE/4 = 8388608
    if (i >= EEc * 4) return;
    int e = i >> 2;
    float m = out[OFF_MASK + e];
    float4 v = ((const float4*)ea)[i];
    if (m == 0.0f) v = make_float4(0.f, 0.f, 0.f, 0.f);
    ((float4*)(out + OFF_EA))[i] = v;
}

extern "C" void kernel_launch(void* const* d_in, const int* in_sizes, int n_in,
                              void* d_out, int out_size) {
    const float* x   = (const float*)d_in[0];
    const int*   ei  = (const int*)d_in[1];      // [2, E]: row0 = src, row1 = dst
    const float* ea  = (const float*)d_in[2];
    const float* W   = (const float*)d_in[4];
    const float* b   = (const float*)d_in[5];
    float* out = (float*)d_out;

    const int* src = ei;
    const int* dst = ei + EEc;

    k_proj   <<<NN / 8, 256>>>(x, W);            // 8 warps/block
    k_deg    <<<EEc / 256, 256>>>(dst);
    k_dinv   <<<NN / 256, 256>>>(b);
    k_scatter<<<EEc / 256, 256>>>(src, dst);
    k_topk   <<<BB, NPGc>>>(out);
    k_gather <<<BKc / 2, 256>>>(x, out);
    k_edges  <<<EEc / 256, 256>>>(src, dst, out);
    k_ea     <<<(EEc * 4) / 256, 256>>>(ea, out);
}

// round 3
// speedup vs baseline: 1.1367x; 1.1367x over previous
#include <cuda_runtime.h>

// Problem constants (fixed shapes)
#define NN   65536      // total nodes
#define BB   64         // graphs
#define NPGc 1024       // nodes per graph
#define CCc  512        // feature dim
#define EEc  2097152    // edges
#define DEc  16         // edge feat dim
#define KKc  512        // k
#define BKc  32768      // B*k

// Output layout (float32, reference-return order)
#define OFF_XNEW  0LL
#define OFF_EI    16777216LL
#define OFF_EA    20971520LL
#define OFF_MASK  54525952LL
#define OFF_BATCH 56623104LL
#define OFF_PERM  56655872LL

// Scratch (device globals). Invariant: g_degE is all-zero at kernel_launch
// entry and restored to zero within each replay. g_score is rewritten fresh
// by k_dinv every replay before the scatter accumulates into it.
__device__ float g_h[NN];       // h, then hd = h*dinv
__device__ float g_dinv[NN];
__device__ float g_score[NN];
__device__ int   g_degE[NN];    // edge in-degree (zeroed in k_dinv)
__device__ int   g_newidx[NN];
__device__ int   g_perm[BKc];

#define PROJ_BLOCKS 8192        // NN/8 rows-per-block warps
#define DEG_BLOCKS  2048        // (E/4)/256

// K1: fused  h = x@W (warp/row)  ||  in-degree atomics (int, 4 edges/thread)
__global__ void k_proj_deg(const float* __restrict__ x, const float* __restrict__ W,
                           const int* __restrict__ dst) {
    if (blockIdx.x < PROJ_BLOCKS) {
        int warp = (blockIdx.x * blockDim.x + threadIdx.x) >> 5;
        int lane = threadIdx.x & 31;
        const float4* xr = (const float4*)(x + (size_t)warp * CCc);
        const float4* w4 = (const float4*)W;
        float s = 0.f;
#pragma unroll
        for (int i = 0; i < 4; i++) {
            float4 a = xr[lane + i * 32];
            float4 w = w4[lane + i * 32];
            s += a.x * w.x + a.y * w.y + a.z * w.z + a.w * w.w;
        }
#pragma unroll
        for (int o = 16; o; o >>= 1) s += __shfl_down_sync(0xffffffffu, s, o);
        if (lane == 0) {
            g_h[warp] = s;
            g_newidx[warp] = -1;
        }
    } else {
        int idx = (blockIdx.x - PROJ_BLOCKS) * 256 + threadIdx.x;   // < E/4
        int4 d4 = ((const int4*)dst)[idx];
        atomicAdd(&g_degE[d4.x], 1);
        atomicAdd(&g_degE[d4.y], 1);
        atomicAdd(&g_degE[d4.z], 1);
        atomicAdd(&g_degE[d4.w], 1);
    }
}

// K2: dinv = rsqrt(1+degE); hd = h*dinv; score = hd*dinv + b; reset degE
__global__ void k_dinv(const float* __restrict__ b) {
    int i = blockIdx.x * blockDim.x + threadIdx.x;
    float dv = rsqrtf(1.0f + (float)g_degE[i]);
    g_dinv[i] = dv;
    float hd = g_h[i] * dv;
    g_h[i] = hd;
    g_score[i] = hd * dv + b[0];
    g_degE[i] = 0;
}

// K3: score[d] += hd[s] * dinv[d]   (4 edges/thread, MLP=4)
// NOTE: term must be the per-edge product (matches reference rounding);
// do NOT factor dinv out of the sum — it perturbs the top-k ranking.
__global__ void k_scatter(const int* __restrict__ src, const int* __restrict__ dst) {
    int idx = blockIdx.x * blockDim.x + threadIdx.x;    // < E/4
    int4 s4 = ((const int4*)src)[idx];
    int4 d4 = ((const int4*)dst)[idx];
    float h0 = g_h[s4.x], h1 = g_h[s4.y], h2 = g_h[s4.z], h3 = g_h[s4.w];
    float v0 = g_dinv[d4.x], v1 = g_dinv[d4.y], v2 = g_dinv[d4.z], v3 = g_dinv[d4.w];
    atomicAdd(&g_score[d4.x], h0 * v0);
    atomicAdd(&g_score[d4.y], h1 * v1);
    atomicAdd(&g_score[d4.z], h2 * v2);
    atomicAdd(&g_score[d4.w], h3 * v3);
}

// K4: per-graph top-k bitonic sort of (descending score, ascending idx)
__global__ void k_topk(float* __restrict__ out) {
    __shared__ unsigned long long keys[NPGc];
    int g = blockIdx.x, t = threadIdx.x;
    int node = g * NPGc + t;
    float sc = g_score[node];
    unsigned int u = __float_as_uint(sc);
    u = (u & 0x80000000u) ? ~u : (u | 0x80000000u);
    u = ~u;                                  // ascending key == descending score
    keys[t] = ((unsigned long long)u << 32) | (unsigned int)t;
    __syncthreads();
    for (int k = 2; k <= NPGc; k <<= 1) {
        for (int j = k >> 1; j > 0; j >>= 1) {
            int ixj = t ^ j;
            if (ixj > t) {
                bool up = ((t & k) == 0);
                unsigned long long a = keys[t], bb = keys[ixj];
                if ((a > bb) == up) { keys[t] = bb; keys[ixj] = a; }
            }
            __syncthreads();
        }
    }
    if (t < KKc) {
        int li = (int)(keys[t] & 0xFFFFFFFFu);
        int n2 = g * NPGc + li;
        int p = g * KKc + t;
        g_perm[p] = n2;
        g_newidx[n2] = p;
        out[OFF_PERM + p]  = (float)n2;
        out[OFF_BATCH + p] = (float)g;
    }
}

#define GATHER_BLOCKS 16384     // BK/2 rows, 2 rows/block
#define EDGE_BLOCKS   8192      // 256 edges/block (32 per warp)

// K5: fused epilogue.
//   blocks [0, GATHER_BLOCKS): x_new = x[perm] * tanh(score[perm])
//   blocks [GATHER_BLOCKS, +EDGE_BLOCKS): ei remap + mask + masked edge_attr copy
__global__ void k_epilogue(const float* __restrict__ x,
                           const int* __restrict__ src, const int* __restrict__ dst,
                           const float* __restrict__ ea, float* __restrict__ out) {
    if (blockIdx.x < GATHER_BLOCKS) {
        int row  = blockIdx.x * 2 + (threadIdx.x >> 7);
        int col4 = threadIdx.x & 127;
        int srcn = g_perm[row];
        float sc = tanhf(g_score[srcn]);
        float4 v = ((const float4*)(x + (size_t)srcn * CCc))[col4];
        v.x *= sc; v.y *= sc; v.z *= sc; v.w *= sc;
        ((float4*)(out + OFF_XNEW + (size_t)row * CCc))[col4] = v;
    } else {
        int wg   = ((blockIdx.x - GATHER_BLOCKS) * 256 + threadIdx.x) >> 5; // global warp
        int lane = threadIdx.x & 31;
        int e = wg * 32 + lane;
        int ns = g_newidx[src[e]];
        int nd = g_newidx[dst[e]];
        bool m = (ns >= 0) && (nd >= 0);
        out[OFF_EI + e]       = m ? (float)ns : -1.0f;
        out[OFF_EI + EEc + e] = m ? (float)nd : -1.0f;
        out[OFF_MASK + e]     = m ? 1.0f : 0.0f;
        unsigned mb = __ballot_sync(0xffffffffu, m);
        long base = (long)wg * 128;          // float4 units: 32 edges * 4
        const float4* eav = (const float4*)ea;
        float4* outv = (float4*)(out + OFF_EA);
#pragma unroll
        for (int it = 0; it < 4; it++) {
            int t = it * 32 + lane;
            bool mm = (mb >> (t >> 2)) & 1u;
            float4 v = eav[base + t];
            if (!mm) v = make_float4(0.f, 0.f, 0.f, 0.f);
            outv[base + t] = v;
        }
    }
}

extern "C" void kernel_launch(void* const* d_in, const int* in_sizes, int n_in,
                              void* d_out, int out_size) {
    const float* x   = (const float*)d_in[0];
    const int*   ei  = (const int*)d_in[1];
    const float* ea  = (const float*)d_in[2];
    const float* W   = (const float*)d_in[4];
    const float* b   = (const float*)d_in[5];
    float* out = (float*)d_out;

    const int* src = ei;
    const int* dst = ei + EEc;

    k_proj_deg<<<PROJ_BLOCKS + DEG_BLOCKS, 256>>>(x, W, dst);
    k_dinv    <<<NN / 256, 256>>>(b);
    k_scatter <<<(EEc / 4) / 256, 256>>>(src, dst);
    k_topk    <<<BB, NPGc>>>(out);
    k_epilogue<<<GATHER_BLOCKS + EDGE_BLOCKS, 256>>>(x, src, dst, ea, out);
}

// round 4
// speedup vs baseline: 1.2404x; 1.0912x over previous
#include <cuda_runtime.h>

// Problem constants (fixed shapes)
#define NN   65536
#define BB   64
#define NPGc 1024
#define CCc  512
#define EEc  2097152
#define DEc  16
#define KKc  512
#define BKc  32768

// Output layout (float32, reference-return order)
#define OFF_XNEW  0LL
#define OFF_EI    16777216LL
#define OFF_EA    20971520LL
#define OFF_MASK  54525952LL
#define OFF_BATCH 56623104LL
#define OFF_PERM  56655872LL

// Scratch. Invariant: g_degE is zero at entry and restored each replay.
// g_score is rewritten fresh by k_dinv each replay.
__device__ float g_h[NN];       // h, then hd = h*dinv
__device__ float g_dinv[NN];
__device__ float g_score[NN];
__device__ int   g_degE[NN];
__device__ int   g_newidx[NN];
__device__ int   g_perm[BKc];

#define PROJ_BLOCKS 8192
#define DEG_BLOCKS  2048

// K1: fused  h = x@W (warp/row)  ||  in-degree atomics (4 edges/thread)
__global__ void k_proj_deg(const float* __restrict__ x, const float* __restrict__ W,
                           const int* __restrict__ dst) {
    if (blockIdx.x < PROJ_BLOCKS) {
        int warp = (blockIdx.x * blockDim.x + threadIdx.x) >> 5;
        int lane = threadIdx.x & 31;
        const float4* xr = (const float4*)(x + (size_t)warp * CCc);
        const float4* w4 = (const float4*)W;
        float s = 0.f;
#pragma unroll
        for (int i = 0; i < 4; i++) {
            float4 a = xr[lane + i * 32];
            float4 w = w4[lane + i * 32];
            s += a.x * w.x + a.y * w.y + a.z * w.z + a.w * w.w;
        }
#pragma unroll
        for (int o = 16; o; o >>= 1) s += __shfl_down_sync(0xffffffffu, s, o);
        if (lane == 0) {
            g_h[warp] = s;
            g_newidx[warp] = -1;
        }
    } else {
        int idx = (blockIdx.x - PROJ_BLOCKS) * 256 + threadIdx.x;   // < E/4
        int4 d4 = ((const int4*)dst)[idx];
        atomicAdd(&g_degE[d4.x], 1);
        atomicAdd(&g_degE[d4.y], 1);
        atomicAdd(&g_degE[d4.z], 1);
        atomicAdd(&g_degE[d4.w], 1);
    }
}

// K2: dinv = rsqrt(1+degE); hd = h*dinv; score = hd*dinv + b; reset degE
__global__ void k_dinv(const float* __restrict__ b) {
    int i = blockIdx.x * blockDim.x + threadIdx.x;
    float dv = rsqrtf(1.0f + (float)g_degE[i]);
    g_dinv[i] = dv;
    float hd = g_h[i] * dv;
    g_h[i] = hd;
    g_score[i] = hd * dv + b[0];
    g_degE[i] = 0;
}

// K3: score[d] += hd[s] * dinv[d]  (4 edges/thread; per-edge product matches
// reference rounding — do NOT factor dinv out of the sum)
__global__ void k_scatter(const int* __restrict__ src, const int* __restrict__ dst) {
    int idx = blockIdx.x * blockDim.x + threadIdx.x;    // < E/4
    int4 s4 = ((const int4*)src)[idx];
    int4 d4 = ((const int4*)dst)[idx];
    float h0 = g_h[s4.x], h1 = g_h[s4.y], h2 = g_h[s4.z], h3 = g_h[s4.w];
    float v0 = g_dinv[d4.x], v1 = g_dinv[d4.y], v2 = g_dinv[d4.z], v3 = g_dinv[d4.w];
    atomicAdd(&g_score[d4.x], h0 * v0);
    atomicAdd(&g_score[d4.y], h1 * v1);
    atomicAdd(&g_score[d4.z], h2 * v2);
    atomicAdd(&g_score[d4.w], h3 * v3);
}

// K4: per-graph top-k via hybrid bitonic sort:
//   j<=16 stages in registers via shfl_xor (no barriers), j>=32 in shared.
// Key: (~monotone(score) << 32) | idx  -> ascending key == (desc score, asc idx)
__global__ void k_topk(float* __restrict__ out) {
    __shared__ unsigned long long keys[NPGc];
    int g = blockIdx.x, t = threadIdx.x;
    int node = g * NPGc + t;
    float sc = g_score[node];
    unsigned int u = __float_as_uint(sc);
    u = (u & 0x80000000u) ? ~u : (u | 0x80000000u);
    u = ~u;
    unsigned long long v = ((unsigned long long)u << 32) | (unsigned int)t;

    // k = 2..32: fully in-warp
#pragma unroll
    for (int k = 2; k <= 32; k <<= 1) {
        bool up = ((t & k) == 0);
#pragma unroll
        for (int j = k >> 1; j >= 1; j >>= 1) {
            unsigned long long o = __shfl_xor_sync(0xffffffffu, v, j);
            bool keepmin = (up == ((t & j) == 0));
            bool takeo = keepmin ? (o < v) : (o > v);
            if (takeo) v = o;
        }
    }
    keys[t] = v;
    __syncthreads();

    for (int k = 64; k <= NPGc; k <<= 1) {
        bool up = ((t & k) == 0);
        // cross-warp stages
        for (int j = k >> 1; j >= 32; j >>= 1) {
            int ixj = t ^ j;
            if (ixj > t) {
                unsigned long long a = keys[t], bb = keys[ixj];
                if ((a > bb) == up) { keys[t] = bb; keys[ixj] = a; }
            }
            __syncthreads();
        }
        // in-warp stages j = 16..1
        v = keys[t];
#pragma unroll
        for (int j = 16; j >= 1; j >>= 1) {
            unsigned long long o = __shfl_xor_sync(0xffffffffu, v, j);
            bool keepmin = (up == ((t & j) == 0));
            bool takeo = keepmin ? (o < v) : (o > v);
            if (takeo) v = o;
        }
        keys[t] = v;
        __syncthreads();
    }

    if (t < KKc) {
        int li = (int)(keys[t] & 0xFFFFFFFFu);
        int n2 = g * NPGc + li;
        int p = g * KKc + t;
        g_perm[p] = n2;
        g_newidx[n2] = p;
        out[OFF_PERM + p]  = (float)n2;
        out[OFF_BATCH + p] = (float)g;
    }
}

#define GATHER_BLOCKS 16384
#define EDGE_BLOCKS   8192

// K5: fused epilogue: x_new gather || ei remap + mask + masked ea copy
// (ea read is predicated on the mask -> skips ~75% of the 134MB read)
__global__ void k_epilogue(const float* __restrict__ x,
                           const int* __restrict__ src, const int* __restrict__ dst,
                           const float* __restrict__ ea, float* __restrict__ out) {
    if (blockIdx.x < GATHER_BLOCKS) {
        int row  = blockIdx.x * 2 + (threadIdx.x >> 7);
        int col4 = threadIdx.x & 127;
        int srcn = g_perm[row];
        float sc = tanhf(g_score[srcn]);
        float4 v = ((const float4*)(x + (size_t)srcn * CCc))[col4];
        v.x *= sc; v.y *= sc; v.z *= sc; v.w *= sc;
        ((float4*)(out + OFF_XNEW + (size_t)row * CCc))[col4] = v;
    } else {
        int wg   = ((blockIdx.x - GATHER_BLOCKS) * 256 + threadIdx.x) >> 5;
        int lane = threadIdx.x & 31;
        int e = wg * 32 + lane;
        int ns = g_newidx[src[e]];
        int nd = g_newidx[dst[e]];
        bool m = (ns >= 0) && (nd >= 0);
        out[OFF_EI + e]       = m ? (float)ns : -1.0f;
        out[OFF_EI + EEc + e] = m ? (float)nd : -1.0f;
        out[OFF_MASK + e]     = m ? 1.0f : 0.0f;
        unsigned mb = __ballot_sync(0xffffffffu, m);
        long base = (long)wg * 128;
        const float4* eav = (const float4*)ea;
        float4* outv = (float4*)(out + OFF_EA);
#pragma unroll
        for (int it = 0; it < 4; it++) {
            int t = it * 32 + lane;
            bool mm = (mb >> (t >> 2)) & 1u;
            float4 v = make_float4(0.f, 0.f, 0.f, 0.f);
            if (mm) v = eav[base + t];
            outv[base + t] = v;
        }
    }
}

extern "C" void kernel_launch(void* const* d_in, const int* in_sizes, int n_in,
                              void* d_out, int out_size) {
    const float* x   = (const float*)d_in[0];
    const int*   ei  = (const int*)d_in[1];
    const float* ea  = (const float*)d_in[2];
    const float* W   = (const float*)d_in[4];
    const float* b   = (const float*)d_in[5];
    float* out = (float*)d_out;

    const int* src = ei;
    const int* dst = ei + EEc;

    k_proj_deg<<<PROJ_BLOCKS + DEG_BLOCKS, 256>>>(x, W, dst);
    k_dinv    <<<NN / 256, 256>>>(b);
    k_scatter <<<(EEc / 4) / 256, 256>>>(src, dst);
    k_topk    <<<BB, NPGc>>>(out);
    k_epilogue<<<GATHER_BLOCKS + EDGE_BLOCKS, 256>>>(x, src, dst, ea, out);
}